// round 5
// baseline (speedup 1.0000x reference)
#include <cuda_runtime.h>

#define BATCH   4096
#define L_IN    16384
#define L_OUT   2044
#define TAPS    36              // composite kernel: 4*5 + 2*5 + 5 + 1
#define NOUT    8               // outputs per thread
#define TPB     128
#define TILE_OUT 1024           // outputs per block (TPB * NOUT)
#define TILE_IN_Q 2056          // quads staged per tile (8224 floats; window needs 8220)
// pad: 4 floats per 64 -> quad index ipq = q + (q>>4)
#define SMEM_Q  (TILE_IN_Q + (TILE_IN_Q >> 4) + 2)   // 2186 quads

__global__ __launch_bounds__(TPB) void encoder_fused_kernel(
    const float* __restrict__ x,
    const float* __restrict__ w1, const float* __restrict__ b1,
    const float* __restrict__ w2, const float* __restrict__ b2,
    const float* __restrict__ w3, const float* __restrict__ b3,
    float* __restrict__ out)
{
    __shared__ float4 xs[SMEM_Q];
    __shared__ float  Wsh[TAPS];
    __shared__ float  Csh;

    const int tid  = threadIdx.x;
    const int row  = blockIdx.x >> 1;
    const int tile = blockIdx.x & 1;
    const int tileStartQ = tile * 2048;     // quad offset of this tile in the row

    // ---- composite weight + bias (tiny, per block) ----
    if (tid < TAPS) {
        float s = 0.0f;
        #pragma unroll
        for (int c = 0; c < 6; c++) {
            #pragma unroll
            for (int b = 0; b < 6; b++) {
                int a = tid - 4 * c - 2 * b;
                if (a >= 0 && a < 6)
                    s += w1[a] * w2[b] * w3[c];
            }
        }
        Wsh[tid] = s;
    }
    if (tid == 0) {
        float S2 = 0.0f, S3 = 0.0f;
        #pragma unroll
        for (int i = 0; i < 6; i++) { S2 += w2[i]; S3 += w3[i]; }
        Csh = b3[0] + b2[0] * S3 + b1[0] * S2 * S3;
    }

    // ---- cooperative coalesced load into padded smem ----
    const float4* src = reinterpret_cast<const float4*>(x) + (size_t)row * (L_IN / 4) + tileStartQ;
    const int nQuad = min(TILE_IN_Q, (L_IN / 4) - tileStartQ);     // 2056 (tile0) / 2048 (tile1)
    #pragma unroll 1
    for (int q = tid; q < TILE_IN_Q; q += TPB) {
        float4 v = (q < nQuad) ? __ldg(src + q) : make_float4(0.f, 0.f, 0.f, 0.f);
        xs[q + (q >> 4)] = v;
    }
    __syncthreads();

    // ---- pull composite weights + bias into registers ----
    float W[TAPS];
    #pragma unroll
    for (int t = 0; t < TAPS; t++) W[t] = Wsh[t];
    const float C = Csh;

    // ---- streaming convolution: 8 outputs per thread ----
    // Thread t: outputs j0..j0+7, window floats [64t, 64t+92) of the tile.
    // Padded base quad index = 17*t (64t floats + 4t pad, /4).
    const float4* wq = &xs[17 * tid];

    float acc[NOUT];
    #pragma unroll
    for (int k = 0; k < NOUT; k++) acc[k] = C;

    #pragma unroll
    for (int m = 0; m < 23; m++) {
        // pad boundary inside window at float 64 (m==16): skip one pad quad
        float4 v = wq[m + (m >= 16 ? 1 : 0)];
        float fl[4] = {v.x, v.y, v.z, v.w};
        #pragma unroll
        for (int j = 0; j < 4; j++) {
            const int d = 4 * m + j;                    // window float index 0..91
            const int klo = (d >= 35) ? ((d - 35 + 7) >> 3) : 0;
            const int khi = (d >> 3) < (NOUT - 1) ? (d >> 3) : (NOUT - 1);
            #pragma unroll
            for (int k = klo; k <= khi; k++)
                acc[k] = fmaf(W[d - 8 * k], fl[j], acc[k]);
        }
    }

    // ---- store ----
    const int j0 = tile * TILE_OUT + tid * NOUT;       // multiple of 8
    float* orow = out + (size_t)row * L_OUT + j0;
    float4 o0 = make_float4(acc[0], acc[1], acc[2], acc[3]);
    *reinterpret_cast<float4*>(orow) = o0;             // j0+3 <= 2043 always
    if (j0 + NOUT <= L_OUT) {
        float4 o1 = make_float4(acc[4], acc[5], acc[6], acc[7]);
        *reinterpret_cast<float4*>(orow + 4) = o1;
    }
}

extern "C" void kernel_launch(void* const* d_in, const int* in_sizes, int n_in,
                              void* d_out, int out_size)
{
    const float* x  = (const float*)d_in[0];
    const float* w1 = (const float*)d_in[1];
    const float* b1 = (const float*)d_in[2];
    const float* w2 = (const float*)d_in[3];
    const float* b2 = (const float*)d_in[4];
    const float* w3 = (const float*)d_in[5];
    const float* b3 = (const float*)d_in[6];
    float* out = (float*)d_out;

    encoder_fused_kernel<<<BATCH * 2, TPB>>>(x, w1, b1, w2, b2, w3, b3, out);
}

// round 7
// speedup vs baseline: 1.7324x; 1.7324x over previous
#include <cuda_runtime.h>

#define BATCH   4096
#define L_IN    16384
#define L_OUT   2044
#define TAPS    36          // composite kernel: 5 + 2*5 + 4*5 + 1
#define NOUT    4           // outputs per task
#define TASKS_PER_ROW (L_OUT / NOUT)     // 511
#define TPB     256
#define TILE_IN_Q 2056      // quads staged per tile (8224 floats; window needs 8220)
// pad: 1 quad per 8 quads (16B per 128B) -> padded quad index = q + (q>>3)
#define SMEM_Q  (TILE_IN_Q + (TILE_IN_Q >> 3) + 1)   // 2314 quads = ~36.2 KB

__global__ __launch_bounds__(TPB) void encoder_fused_kernel(
    const float* __restrict__ x,
    const float* __restrict__ w1, const float* __restrict__ b1,
    const float* __restrict__ w2, const float* __restrict__ b2,
    const float* __restrict__ w3, const float* __restrict__ b3,
    float* __restrict__ out)
{
    __shared__ float4 xs[SMEM_Q];
    __shared__ float  Wsh[TAPS];
    __shared__ float  Csh;

    const int tid  = threadIdx.x;
    const int row  = blockIdx.x >> 1;
    const int tile = blockIdx.x & 1;
    const int tileStartQ = tile * 2048;     // quad offset of this tile within the row

    // ---- composite weight + bias (tiny, per block) ----
    if (tid < TAPS) {
        float s = 0.0f;
        #pragma unroll
        for (int c = 0; c < 6; c++) {
            #pragma unroll
            for (int b = 0; b < 6; b++) {
                int a = tid - 4 * c - 2 * b;
                if (a >= 0 && a < 6)
                    s += w1[a] * w2[b] * w3[c];
            }
        }
        Wsh[tid] = s;
    }
    if (tid == 0) {
        float S2 = 0.0f, S3 = 0.0f;
        #pragma unroll
        for (int i = 0; i < 6; i++) { S2 += w2[i]; S3 += w3[i]; }
        Csh = b3[0] + b2[0] * S3 + b1[0] * S2 * S3;
    }

    // ---- async coalesced load into padded smem (L1-bypassing, reg-free) ----
    const float4* src = reinterpret_cast<const float4*>(x)
                        + (size_t)row * (L_IN / 4) + tileStartQ;
    const int nQuad = min(TILE_IN_Q, (L_IN / 4) - tileStartQ);  // 2056 (tile0) / 2048 (tile1)

    #pragma unroll
    for (int it = 0; it < 9; it++) {
        int q = tid + it * TPB;
        if (q < TILE_IN_Q) {
            // src_size = 0 -> hardware zero-fill for out-of-row quads (tile1 tail)
            int srcBytes = (q < nQuad) ? 16 : 0;
            unsigned sdst = (unsigned)__cvta_generic_to_shared(&xs[q + (q >> 3)]);
            asm volatile("cp.async.cg.shared.global [%0], [%1], 16, %2;\n"
                         :: "r"(sdst), "l"(src + q), "r"(srcBytes));
        }
    }
    asm volatile("cp.async.commit_group;\n" ::: "memory");
    asm volatile("cp.async.wait_group 0;\n" ::: "memory");
    __syncthreads();

    // ---- compute: each thread = 4 consecutive outputs ----
    const int task = tile * TPB + tid;          // 0..511 (511 invalid)
    if (task < TASKS_PER_ROW) {
        // window floats [32*tid, 32*tid + 60) of this tile = 15 quads,
        // padded base quad = 9*tid, +1 extra skip for m >= 8
        const float4* wq = &xs[9 * tid];

        float f[60];
        #pragma unroll
        for (int m = 0; m < 15; m++) {
            float4 v = wq[m + (m >= 8 ? 1 : 0)];
            f[4 * m + 0] = v.x;
            f[4 * m + 1] = v.y;
            f[4 * m + 2] = v.z;
            f[4 * m + 3] = v.w;
        }

        const float C = Csh;
        float acc[NOUT];
        #pragma unroll
        for (int k = 0; k < NOUT; k++) {
            float a = C;
            #pragma unroll
            for (int t = 0; t < TAPS; t++)
                a = fmaf(Wsh[t], f[8 * k + t], a);
            acc[k] = a;
        }

        float4 o = make_float4(acc[0], acc[1], acc[2], acc[3]);
        float4* op = reinterpret_cast<float4*>(out + (size_t)row * L_OUT + task * NOUT);
        __stcs(op, o);   // streaming store, evict-first
    }
}

extern "C" void kernel_launch(void* const* d_in, const int* in_sizes, int n_in,
                              void* d_out, int out_size)
{
    const float* x  = (const float*)d_in[0];
    const float* w1 = (const float*)d_in[1];
    const float* b1 = (const float*)d_in[2];
    const float* w2 = (const float*)d_in[3];
    const float* b2 = (const float*)d_in[4];
    const float* w3 = (const float*)d_in[5];
    const float* b3 = (const float*)d_in[6];
    float* out = (float*)d_out;

    encoder_fused_kernel<<<BATCH * 2, TPB>>>(x, w1, b1, w2, b2, w3, b3, out);
}

// round 8
// speedup vs baseline: 1.9941x; 1.1511x over previous
#include <cuda_runtime.h>

#define BATCH   4096
#define L_IN    16384
#define L_OUT   2044
#define TAPS    36          // composite kernel: 5 + 2*5 + 4*5 + 1
#define NOUT    4           // outputs per task
#define TASKS_PER_ROW (L_OUT / NOUT)     // 511
#define TPB     256
#define TILE_IN_Q 2056      // quads staged per tile (window needs 2055)
// pad: 1 quad per 8 quads -> padded quad index = q + (q>>3)
#define SMEM_Q  (TILE_IN_Q + (TILE_IN_Q >> 3) + 1)   // 2314 quads = 37,024 B per buffer
#define GRID    2048
#define TPT     4           // tiles per block (GRID * TPT = 8192 tiles)
#define DYN_SMEM_BYTES (2 * SMEM_Q * 16)

__device__ __forceinline__ void issue_tile_load(float4* buf, const float4* x4, int t)
{
    const int row  = t >> 1;
    const int half = t & 1;
    const float4* src = x4 + (size_t)row * (L_IN / 4) + half * 2048;
    const int nQuad = half ? 2048 : TILE_IN_Q;     // tile1 tail is OOB -> zero-fill
    const int tid = threadIdx.x;
    #pragma unroll
    for (int it = 0; it < 9; it++) {
        int q = tid + it * TPB;
        if (q < TILE_IN_Q) {
            int srcBytes = (q < nQuad) ? 16 : 0;
            unsigned sdst = (unsigned)__cvta_generic_to_shared(&buf[q + (q >> 3)]);
            asm volatile("cp.async.cg.shared.global [%0], [%1], 16, %2;\n"
                         :: "r"(sdst), "l"(src + q), "r"(srcBytes));
        }
    }
    asm volatile("cp.async.commit_group;\n" ::: "memory");
}

__global__ __launch_bounds__(TPB) void encoder_fused_kernel(
    const float* __restrict__ x,
    const float* __restrict__ w1, const float* __restrict__ b1,
    const float* __restrict__ w2, const float* __restrict__ b2,
    const float* __restrict__ w3, const float* __restrict__ b3,
    float* __restrict__ out)
{
    extern __shared__ float4 xs[];            // 2 buffers of SMEM_Q quads
    __shared__ float Wsh[TAPS];
    __shared__ float Csh;

    const int tid = threadIdx.x;

    // ---- composite weight + bias (tiny, per block) ----
    if (tid < TAPS) {
        float s = 0.0f;
        #pragma unroll
        for (int c = 0; c < 6; c++) {
            #pragma unroll
            for (int b = 0; b < 6; b++) {
                int a = tid - 4 * c - 2 * b;
                if (a >= 0 && a < 6)
                    s += w1[a] * w2[b] * w3[c];
            }
        }
        Wsh[tid] = s;
    }
    if (tid == 0) {
        float S2 = 0.0f, S3 = 0.0f;
        #pragma unroll
        for (int i = 0; i < 6; i++) { S2 += w2[i]; S3 += w3[i]; }
        Csh = b3[0] + b2[0] * S3 + b1[0] * S2 * S3;
    }

    const float4* x4 = reinterpret_cast<const float4*>(x);
    const int tbase = blockIdx.x * TPT;

    // prologue: prefetch first tile into buffer 0
    issue_tile_load(&xs[0], x4, tbase);

    #pragma unroll 1
    for (int i = 0; i < TPT; i++) {
        const int t = tbase + i;
        float4* cur = &xs[(i & 1) ? SMEM_Q : 0];
        float4* nxt = &xs[(i & 1) ? 0 : SMEM_Q];

        asm volatile("cp.async.wait_group 0;\n" ::: "memory");
        __syncthreads();   // cur loaded; everyone done reading nxt (prev compute)

        if (i + 1 < TPT)
            issue_tile_load(nxt, x4, t + 1);   // overlaps with compute below

        // ---- compute: each thread = 4 consecutive outputs of tile t ----
        const int row  = t >> 1;
        const int half = t & 1;
        const int task = half * TPB + tid;     // 0..511 (511 invalid)
        if (task < TASKS_PER_ROW) {
            const float4* wq = &cur[9 * tid];  // window = 15 quads, pad skip at m>=8
            float f[60];
            #pragma unroll
            for (int m = 0; m < 15; m++) {
                float4 v = wq[m + (m >= 8 ? 1 : 0)];
                f[4 * m + 0] = v.x;
                f[4 * m + 1] = v.y;
                f[4 * m + 2] = v.z;
                f[4 * m + 3] = v.w;
            }

            const float C = Csh;
            float acc[NOUT];
            #pragma unroll
            for (int k = 0; k < NOUT; k++) {
                float a = C;
                #pragma unroll
                for (int tt = 0; tt < TAPS; tt++)
                    a = fmaf(Wsh[tt], f[8 * k + tt], a);
                acc[k] = a;
            }

            float4 o = make_float4(acc[0], acc[1], acc[2], acc[3]);
            float4* op = reinterpret_cast<float4*>(out + (size_t)row * L_OUT + task * NOUT);
            __stcs(op, o);
        }
    }
}

extern "C" void kernel_launch(void* const* d_in, const int* in_sizes, int n_in,
                              void* d_out, int out_size)
{
    const float* x  = (const float*)d_in[0];
    const float* w1 = (const float*)d_in[1];
    const float* b1 = (const float*)d_in[2];
    const float* w2 = (const float*)d_in[3];
    const float* b2 = (const float*)d_in[4];
    const float* w3 = (const float*)d_in[5];
    const float* b3 = (const float*)d_in[6];
    float* out = (float*)d_out;

    static int configured = 0;
    if (!configured) {
        cudaFuncSetAttribute(encoder_fused_kernel,
                             cudaFuncAttributeMaxDynamicSharedMemorySize,
                             DYN_SMEM_BYTES);
        configured = 1;
    }

    encoder_fused_kernel<<<GRID, TPB, DYN_SMEM_BYTES>>>(x, w1, b1, w2, b2, w3, b3, out);
}